// round 14
// baseline (speedup 1.0000x reference)
#include <cuda_runtime.h>
#include <cstdint>

#define BS      128
#define NQ      900
#define NC      91
#define NTOT    (NQ * NC)     /* 81900 */
#define NVEC    (NTOT / 4)    /* 20475 */
#define TSEL    160
#define SORT_N  256
#define NPOST   100
#define NBINS   8192
#define NTHREADS 1024
#define IOU_THR 0.7f
#define MROW    256           /* matrix-NMS depth == SORT_N */
#define WBUF    48            /* per-warp candidate buffer */

// ---- XLA logistic replica: 0.5 + 0.5 * fast_tanh(0.5 * x), non-fused ----
__device__ __forceinline__ float xla_logistic(float x) {
    float t_in = __fmul_rn(x, 0.5f);
    float ax = fabsf(t_in);
    float t;
    if (ax < 0.0004f) {
        t = t_in;
    } else {
        float xc = fminf(fmaxf(t_in, -9.0f), 9.0f);
        float x2 = __fmul_rn(xc, xc);
        float p = -2.76076847742355e-16f;
        p = __fadd_rn(__fmul_rn(p, x2), 2.00018790482477e-13f);
        p = __fadd_rn(__fmul_rn(p, x2), -8.60467152213735e-11f);
        p = __fadd_rn(__fmul_rn(p, x2), 5.12229709037114e-08f);
        p = __fadd_rn(__fmul_rn(p, x2), 1.48572235717979e-05f);
        p = __fadd_rn(__fmul_rn(p, x2), 6.37261928875436e-04f);
        p = __fadd_rn(__fmul_rn(p, x2), 4.89352455891786e-03f);
        p = __fmul_rn(p, xc);
        float q = 1.19825839466702e-06f;
        q = __fadd_rn(__fmul_rn(q, x2), 1.18534705686654e-04f);
        q = __fadd_rn(__fmul_rn(q, x2), 2.26843463243900e-03f);
        q = __fadd_rn(__fmul_rn(q, x2), 4.89352518554385e-03f);
        t = __fdiv_rn(p, q);
    }
    return __fadd_rn(0.5f, __fmul_rn(0.5f, t));
}

__device__ __forceinline__ unsigned int ordered_bits(float x) {
    unsigned int u = __float_as_uint(x);
    int s = ((int)u) >> 31;
    return u ^ ((unsigned int)s | 0x80000000u);
}

__device__ __forceinline__ unsigned int inv_ordered(unsigned int ob) {
    return (ob & 0x80000000u) ? (ob ^ 0x80000000u) : ~ob;
}

struct __align__(16) ShKeysBoxes {
    unsigned long long keys[SORT_N];   // 2 KB (unsorted candidates)
    float4 cbox[SORT_N];               // 4 KB
    float  area[SORT_N];               // 1 KB
    int    clab[SORT_N];               // 1 KB
};

__global__ __launch_bounds__(NTHREADS, 1)
void nms_post_kernel(const float* __restrict__ logits,
                     const float* __restrict__ boxes,
                     const float* __restrict__ tsz,
                     float* __restrict__ out) {
    extern __shared__ float4 s_bmax4[];        // 5*1024 float4 = 80 KB dynamic
    __shared__ union {
        unsigned int hist[NBINS];      // 32 KB (threshold phase only)
        ShKeysBoxes  s;                // 8 KB (later phases)
    } U;
    __shared__ unsigned int s_coarse[NTHREADS];
    __shared__ unsigned int s_wtot[32];
    __shared__ unsigned long long s_mat64[MROW * 4];       // 8 KB
    __shared__ unsigned long long s_wbuf[32][WBUF];        // 12 KB (also: sorted keys)
    __shared__ float4 s_qbox[NQ];                          // 14.4 KB scaled xyxy
    __shared__ int s_wc[32];
    __shared__ int s_wbase[32];
    __shared__ int s_pkj[NPOST];
    __shared__ int s_cnt, s_bin, s_g;

    const int img = blockIdx.x;
    const int tid = threadIdx.x;
    const int lane = tid & 31;
    const int wid = tid >> 5;

    const float4* lg4 = reinterpret_cast<const float4*>(logits + (size_t)img * NTOT);
    const float4* bx4 = reinterpret_cast<const float4*>(boxes + (size_t)img * NQ * 4);
    const float img_h = tsz[img * 2 + 0];
    const float img_w = tsz[img * 2 + 1];

    const float NEG = __int_as_float(0xff800000);   // -inf
    const float4 NEG4 = make_float4(NEG, NEG, NEG, NEG);

    // ---- init hoisted under Pass A's DRAM latency:
    //      zero hist, zero matrix, precompute 900 scaled xyxy boxes ----
    {
        uint4* h4 = reinterpret_cast<uint4*>(U.hist);
        const uint4 z = make_uint4(0u, 0u, 0u, 0u);
        h4[tid * 2 + 0] = z;
        h4[tid * 2 + 1] = z;
        s_mat64[tid] = 0ull;                       // MROW*4 == 1024
        if (tid < NQ) {
            float4 b = bx4[tid];
            s_qbox[tid] = make_float4((b.x - 0.5f * b.z) * img_w,
                                      (b.y - 0.5f * b.w) * img_h,
                                      (b.x + 0.5f * b.z) * img_w,
                                      (b.y + 0.5f * b.w) * img_h);
        }
    }

    // ---- Pass A: per-thread max; 4 group maxima per iter -> one STS.128 ----
    float m = NEG;
    #pragma unroll 1
    for (int it = 0; it < 5; ++it) {
        const int i0 = it * (4 * NTHREADS) + tid;
        const int i1 = i0 + NTHREADS;
        const int i2 = i1 + NTHREADS;
        const int i3 = i2 + NTHREADS;
        float4 v0 = lg4[i0];                       // max 17407 < NVEC
        float4 v1 = lg4[i1];                       // max 18431 < NVEC
        float4 v2 = lg4[i2];                       // max 19455 < NVEC
        float4 v3 = (i3 < NVEC) ? lg4[i3] : NEG4;  // only slot that can OOB
        float m0 = fmaxf(fmaxf(v0.x, v0.y), fmaxf(v0.z, v0.w));
        float m1 = fmaxf(fmaxf(v1.x, v1.y), fmaxf(v1.z, v1.w));
        float m2 = fmaxf(fmaxf(v2.x, v2.y), fmaxf(v2.z, v2.w));
        float m3 = fmaxf(fmaxf(v3.x, v3.y), fmaxf(v3.z, v3.w));
        s_bmax4[tid * 5 + it] = make_float4(m0, m1, m2, m3);
        m = fmaxf(m, fmaxf(fmaxf(m0, m1), fmaxf(m2, m3)));
    }
    __syncthreads();   // init + bmax visible

    // ---- Threshold: histogram of 1024 per-thread maxima -> bin ----
    atomicAdd(&U.hist[ordered_bits(m) >> 19], 1u);
    __syncthreads();
    unsigned int csum;
    {
        const uint4* h4 = reinterpret_cast<const uint4*>(U.hist);
        uint4 a = h4[tid * 2 + 0];
        uint4 b = h4[tid * 2 + 1];
        csum = a.x + a.y + a.z + a.w + b.x + b.y + b.z + b.w;
    }
    {
        unsigned int val = csum;
        #pragma unroll
        for (int off = 1; off < 32; off <<= 1) {
            unsigned int v = __shfl_down_sync(0xffffffffu, val, off);
            if (lane + off < 32) val += v;
        }
        if (lane == 0) s_wtot[wid] = val;
        __syncthreads();
        if (tid < 32) {
            unsigned int w = s_wtot[tid];
            #pragma unroll
            for (int off = 1; off < 32; off <<= 1) {
                unsigned int v = __shfl_down_sync(0xffffffffu, w, off);
                if (tid + off < 32) w += v;
            }
            s_wtot[tid] = w;
        }
        __syncthreads();
        s_coarse[tid] = val + ((wid < 31) ? s_wtot[wid + 1] : 0u);
    }
    __syncthreads();
    {
        unsigned int mine = s_coarse[tid];
        unsigned int nxt = (tid < NTHREADS - 1) ? s_coarse[tid + 1] : 0u;
        if (mine >= TSEL && nxt < TSEL) s_g = tid;
    }
    __syncthreads();
    if (tid == 0) {
        int g = s_g;
        unsigned int cum = (g < NTHREADS - 1) ? s_coarse[g + 1] : 0u;
        int b = g * 8;
        for (int bin = g * 8 + 7; bin >= g * 8; --bin) {
            cum += U.hist[bin];
            if (cum >= TSEL) { b = bin; break; }
        }
        s_bin = b;
    }
    __syncthreads();
    const float thr_float = __uint_as_float(inv_ordered((unsigned int)s_bin << 19));
    __syncthreads();   // all hist reads done before keys alias

    // ---- Pass B: gate on vector maxima (5 LDS.128, guard-free);
    //      collect into warp-private buffers ----
    if (tid < SORT_N) U.s.keys[tid] = 0ull;
    if (tid < 32) s_wc[tid] = 0;
    __syncthreads();
    #pragma unroll 1
    for (int it = 0; it < 5; ++it) {
        float4 bm = s_bmax4[tid * 5 + it];
        const float bms[4] = {bm.x, bm.y, bm.z, bm.w};
        #pragma unroll
        for (int u = 0; u < 4; ++u) {
            if (bms[u] >= thr_float) {     // gate pass implies load in-bounds
                int i = it * (4 * NTHREADS) + u * NTHREADS + tid;
                float4 v = lg4[i];         // L2 hit
                const float vv[4] = {v.x, v.y, v.z, v.w};
                #pragma unroll
                for (int c = 0; c < 4; ++c) {
                    if (vv[c] >= thr_float) {
                        float p = xla_logistic(vv[c]);
                        int pos = atomicAdd(&s_wc[wid], 1);   // 32 banks
                        if (pos < WBUF) {
                            s_wbuf[wid][pos] =
                                ((unsigned long long)__float_as_uint(p) << 32)
                              | (unsigned int)(~(i * 4 + c));
                        }
                    }
                }
            }
        }
    }
    __syncthreads();

    // ---- warp bases via 32-wide scan; copy warp buffers to contiguous keys ----
    if (tid < 32) {
        int c = s_wc[tid]; if (c > WBUF) c = WBUF;
        int v = c;
        #pragma unroll
        for (int off = 1; off < 32; off <<= 1) {
            int u = __shfl_up_sync(0xffffffffu, v, off);
            if (lane >= off) v += u;
        }
        s_wbase[tid] = v - c;
        if (tid == 31) s_cnt = v;
    }
    __syncthreads();
    {
        int myc = s_wc[wid]; if (myc > WBUF) myc = WBUF;
        int base = s_wbase[wid];
        for (int p = lane; p < myc; p += 32) {
            int pos = base + p;
            if (pos < SORT_N) U.s.keys[pos] = s_wbuf[wid][p];
        }
    }
    __syncthreads();
    const int cnt = (s_cnt < SORT_N) ? s_cnt : SORT_N;

    // ---- Rank-scatter sort (keys unique): 4 threads per key, 1 barrier ----
    unsigned long long* sorted = &s_wbuf[0][0];   // reuse (>= 2 KB free)
    {
        const int j = tid >> 2;          // 0..255 key owner
        const int part = tid & 3;        // 64-key slice per part
        unsigned long long mykey = U.s.keys[j];
        const ulonglong2* k2 = reinterpret_cast<const ulonglong2*>(U.s.keys);
        int r = 0;
        #pragma unroll 4
        for (int t = 0; t < 32; ++t) {
            ulonglong2 kk = k2[part * 32 + t];   // broadcast LDS.128
            r += (kk.x > mykey) + (kk.y > mykey);
        }
        r += __shfl_xor_sync(0xffffffffu, r, 1);
        r += __shfl_xor_sync(0xffffffffu, r, 2);
        if (part == 0 && j < cnt) sorted[r] = mykey;   // descending order
    }
    __syncthreads();

    // ---- Candidate boxes: gather from SMEM table (no LDG) ----
    if (tid < SORT_N) {
        const int j = tid;
        if (j < cnt) {
            unsigned long long key = sorted[j];
            int idx = (int)(~(unsigned int)key);
            int q = idx / NC, lbl = idx - q * NC;
            float4 bb = s_qbox[q];
            U.s.cbox[j] = bb;
            U.s.area[j] = (bb.z - bb.x) * (bb.w - bb.y);
            U.s.clab[j] = lbl;
        } else {
            U.s.cbox[j] = make_float4(0.f, 0.f, 0.f, 0.f);
            U.s.area[j] = 0.f;
            U.s.clab[j] = -1;
        }
    }
    __syncthreads();

    // ---- Matrix build: sup bits for i,j < 256 (label-gated, div-free) ----
    {
        const int i = tid >> 2;          // 0..255 row owner
        const int seg = tid & 3;         // 0..3 -> j in [seg*64, seg*64+64)
        float4 bi = U.s.cbox[i];
        float  ai = U.s.area[i];
        int    li = U.s.clab[i];
        const int4* clab4 = reinterpret_cast<const int4*>(U.s.clab);
        unsigned int* matw = reinterpret_cast<unsigned int*>(s_mat64);
        #pragma unroll 1
        for (int t = 0; t < 16; ++t) {
            int jb = seg * 64 + t * 4;
            int4 l4 = clab4[jb >> 2];    // LDS.128, 4 labels
            #define CHK(COMP, J)                                                 \
            if ((COMP) == li && li >= 0 && (J) != i) {                           \
                float4 bj = U.s.cbox[J];                                         \
                float xx1 = fmaxf(bi.x, bj.x);                                   \
                float yy1 = fmaxf(bi.y, bj.y);                                   \
                float xx2 = fminf(bi.z, bj.z);                                   \
                float yy2 = fminf(bi.w, bj.w);                                   \
                float inter = fmaxf(xx2 - xx1, 0.f) * fmaxf(yy2 - yy1, 0.f);     \
                float uni = fmaxf(ai + U.s.area[J] - inter, 1e-9f);              \
                if (inter > IOU_THR * uni)                                       \
                    atomicOr(&matw[i * 8 + ((J) >> 5)], 1u << ((J) & 31));       \
            }
            CHK(l4.x, jb + 0)
            CHK(l4.y, jb + 1)
            CHK(l4.z, jb + 2)
            CHK(l4.w, jb + 3)
            #undef CHK
        }
    }
    __syncthreads();

    // ---- Serial walk: ffs over 256-bit not-suppressed mask (1 thread) ----
    if (tid == 0) {
        unsigned long long mk[4] = {0ull, 0ull, 0ull, 0ull};
        int npick = 0;
        const int jmax = cnt;   // cnt <= SORT_N == MROW
        const ulonglong2* mat2 = reinterpret_cast<const ulonglong2*>(s_mat64);
        for (int b = 0; b < 4 && npick < NPOST; ++b) {
            int lim = jmax - b * 64;
            if (lim <= 0) break;
            unsigned long long validm =
                (lim >= 64) ? ~0ull : ((1ull << lim) - 1ull);
            unsigned long long rem = ~mk[b] & validm;
            while (rem && npick < NPOST) {
                int jo = __ffsll((long long)rem) - 1;
                int j = b * 64 + jo;
                s_pkj[npick++] = j;
                ulonglong2 r0 = mat2[j * 2 + 0];
                ulonglong2 r1 = mat2[j * 2 + 1];
                mk[0] |= r0.x;
                mk[1] |= r0.y;
                mk[2] |= r1.x;
                mk[3] |= r1.y;
                unsigned long long above =
                    (jo == 63) ? 0ull : (~0ull << (jo + 1));
                rem = ~mk[b] & validm & above;
            }
        }
        // exhaustion padding (reference: argmax over all -inf = index 0)
        for (; npick < NPOST; ++npick) s_pkj[npick] = 0;
    }
    __syncthreads();

    // ---- Outputs [scores | labels | boxes] f32 (boxes from SMEM table) ----
    if (tid < NPOST) {
        const int k = tid;
        int j = s_pkj[k];
        unsigned long long key = sorted[j];
        float score = __uint_as_float((unsigned int)(key >> 32));
        int idx = (int)(~(unsigned int)key);
        int q = idx / NC, lbl = idx - q * NC;
        float4 bb = s_qbox[q];

        out[(size_t)img * NPOST + k] = score;
        out[(size_t)BS * NPOST + (size_t)img * NPOST + k] = (float)lbl;
        float* ob = out + (size_t)2 * BS * NPOST + ((size_t)img * NPOST + k) * 4;
        ob[0] = bb.x; ob[1] = bb.y; ob[2] = bb.z; ob[3] = bb.w;
    }
}

extern "C" void kernel_launch(void* const* d_in, const int* in_sizes, int n_in,
                              void* d_out, int out_size) {
    const float* pred_logits  = (const float*)d_in[0];
    const float* pred_boxes   = (const float*)d_in[1];
    const float* target_sizes = (const float*)d_in[2];
    float* out = (float*)d_out;
    (void)in_sizes; (void)n_in; (void)out_size;
    const int dyn = 5 * NTHREADS * (int)sizeof(float4);   // 80 KB
    cudaFuncSetAttribute((const void*)nms_post_kernel,
                         cudaFuncAttributeMaxDynamicSharedMemorySize, dyn);
    nms_post_kernel<<<BS, NTHREADS, dyn>>>(pred_logits, pred_boxes, target_sizes, out);
}

// round 15
// speedup vs baseline: 1.2960x; 1.2960x over previous
#include <cuda_runtime.h>
#include <cstdint>

#define BS      128
#define NQ      900
#define NC      91
#define NTOT    (NQ * NC)     /* 81900 */
#define NVEC    (NTOT / 4)    /* 20475 */
#define TSEL    160
#define SORT_N  256
#define NPOST   100
#define NBINS   8192
#define NTHREADS 1024
#define IOU_THR 0.7f
#define MROW    256           /* matrix-NMS depth == SORT_N */
#define WBUF    48            /* per-warp candidate buffer */

#define BAR256() asm volatile("bar.sync 1, 256;" ::: "memory")

// ---- XLA logistic replica: 0.5 + 0.5 * fast_tanh(0.5 * x), non-fused ----
__device__ __forceinline__ float xla_logistic(float x) {
    float t_in = __fmul_rn(x, 0.5f);
    float ax = fabsf(t_in);
    float t;
    if (ax < 0.0004f) {
        t = t_in;
    } else {
        float xc = fminf(fmaxf(t_in, -9.0f), 9.0f);
        float x2 = __fmul_rn(xc, xc);
        float p = -2.76076847742355e-16f;
        p = __fadd_rn(__fmul_rn(p, x2), 2.00018790482477e-13f);
        p = __fadd_rn(__fmul_rn(p, x2), -8.60467152213735e-11f);
        p = __fadd_rn(__fmul_rn(p, x2), 5.12229709037114e-08f);
        p = __fadd_rn(__fmul_rn(p, x2), 1.48572235717979e-05f);
        p = __fadd_rn(__fmul_rn(p, x2), 6.37261928875436e-04f);
        p = __fadd_rn(__fmul_rn(p, x2), 4.89352455891786e-03f);
        p = __fmul_rn(p, xc);
        float q = 1.19825839466702e-06f;
        q = __fadd_rn(__fmul_rn(q, x2), 1.18534705686654e-04f);
        q = __fadd_rn(__fmul_rn(q, x2), 2.26843463243900e-03f);
        q = __fadd_rn(__fmul_rn(q, x2), 4.89352518554385e-03f);
        t = __fdiv_rn(p, q);
    }
    return __fadd_rn(0.5f, __fmul_rn(0.5f, t));
}

__device__ __forceinline__ unsigned int ordered_bits(float x) {
    unsigned int u = __float_as_uint(x);
    int s = ((int)u) >> 31;
    return u ^ ((unsigned int)s | 0x80000000u);
}

__device__ __forceinline__ unsigned int inv_ordered(unsigned int ob) {
    return (ob & 0x80000000u) ? (ob ^ 0x80000000u) : ~ob;
}

__device__ __forceinline__ unsigned long long
bitonic_inwarp(unsigned long long key, int tid, int k, int jstart) {
    for (int j = jstart; j > 0; j >>= 1) {
        unsigned long long other = __shfl_xor_sync(0xffffffffu, key, j);
        bool take_max = (((tid & k) == 0) == ((tid & j) == 0));
        bool gt = key > other;
        key = (take_max == gt) ? key : other;
    }
    return key;
}

struct __align__(16) ShKeysBoxes {
    unsigned long long keys[SORT_N];   // 2 KB
    float4 cbox[SORT_N];               // 4 KB
    float  area[SORT_N];               // 1 KB
    int    clab[SORT_N];               // 1 KB
};

__global__ __launch_bounds__(NTHREADS, 1)
void nms_post_kernel(const float* __restrict__ logits,
                     const float* __restrict__ boxes,
                     const float* __restrict__ tsz,
                     float* __restrict__ out) {
    extern __shared__ float4 s_bmax4[];        // 5*1024 float4 = 80 KB dynamic
    __shared__ union {
        unsigned int hist[NBINS];      // 32 KB (threshold phase only)
        ShKeysBoxes  s;                // 8 KB (later phases)
    } U;
    __shared__ unsigned int s_coarse[NTHREADS];
    __shared__ unsigned int s_wtot[32];
    __shared__ unsigned long long s_mat64[MROW * 4];       // 8 KB
    __shared__ unsigned long long s_wbuf[32][WBUF];        // 12 KB
    __shared__ float4 s_qbox[NQ];                          // 14.4 KB scaled xyxy
    __shared__ int s_wc[32];
    __shared__ int s_wbase[32];
    __shared__ int s_pkj[NPOST];
    __shared__ int s_cnt, s_bin, s_g;

    const int img = blockIdx.x;
    const int tid = threadIdx.x;
    const int lane = tid & 31;
    const int wid = tid >> 5;

    const float4* lg4 = reinterpret_cast<const float4*>(logits + (size_t)img * NTOT);
    const float4* bx4 = reinterpret_cast<const float4*>(boxes + (size_t)img * NQ * 4);
    const float img_h = tsz[img * 2 + 0];
    const float img_w = tsz[img * 2 + 1];

    const float NEG = __int_as_float(0xff800000);   // -inf
    const float4 NEG4 = make_float4(NEG, NEG, NEG, NEG);

    // ---- hist zeroing hoisted (vectorized): hides under Pass A ----
    {
        uint4* h4 = reinterpret_cast<uint4*>(U.hist);
        const uint4 z = make_uint4(0u, 0u, 0u, 0u);
        h4[tid * 2 + 0] = z;
        h4[tid * 2 + 1] = z;
    }

    // ---- Pass A: per-thread max; 4 group maxima -> one conflict-free STS.128 ----
    float m = NEG;
    #pragma unroll 1
    for (int it = 0; it < 5; ++it) {
        const int i0 = it * (4 * NTHREADS) + tid;
        const int i1 = i0 + NTHREADS;
        const int i2 = i1 + NTHREADS;
        const int i3 = i2 + NTHREADS;
        float4 v0 = lg4[i0];                       // max 17407 < NVEC
        float4 v1 = lg4[i1];                       // max 18431 < NVEC
        float4 v2 = lg4[i2];                       // max 19455 < NVEC
        float4 v3 = (i3 < NVEC) ? lg4[i3] : NEG4;  // only slot that can OOB
        float m0 = fmaxf(fmaxf(v0.x, v0.y), fmaxf(v0.z, v0.w));
        float m1 = fmaxf(fmaxf(v1.x, v1.y), fmaxf(v1.z, v1.w));
        float m2 = fmaxf(fmaxf(v2.x, v2.y), fmaxf(v2.z, v2.w));
        float m3 = fmaxf(fmaxf(v3.x, v3.y), fmaxf(v3.z, v3.w));
        s_bmax4[it * NTHREADS + tid] = make_float4(m0, m1, m2, m3);   // 16B stride
        m = fmaxf(m, fmaxf(fmaxf(m0, m1), fmaxf(m2, m3)));
    }
    __syncthreads();   // hist zeroed & bmax written

    // ---- Threshold: histogram of 1024 per-thread maxima -> bin ----
    atomicAdd(&U.hist[ordered_bits(m) >> 19], 1u);
    __syncthreads();
    unsigned int csum;
    {
        const uint4* h4 = reinterpret_cast<const uint4*>(U.hist);
        uint4 a = h4[tid * 2 + 0];
        uint4 b = h4[tid * 2 + 1];
        csum = a.x + a.y + a.z + a.w + b.x + b.y + b.z + b.w;
    }
    {
        unsigned int val = csum;
        #pragma unroll
        for (int off = 1; off < 32; off <<= 1) {
            unsigned int v = __shfl_down_sync(0xffffffffu, val, off);
            if (lane + off < 32) val += v;
        }
        if (lane == 0) s_wtot[wid] = val;
        __syncthreads();
        if (tid < 32) {
            unsigned int w = s_wtot[tid];
            #pragma unroll
            for (int off = 1; off < 32; off <<= 1) {
                unsigned int v = __shfl_down_sync(0xffffffffu, w, off);
                if (tid + off < 32) w += v;
            }
            s_wtot[tid] = w;
        }
        __syncthreads();
        s_coarse[tid] = val + ((wid < 31) ? s_wtot[wid + 1] : 0u);
    }
    __syncthreads();
    {
        unsigned int mine = s_coarse[tid];
        unsigned int nxt = (tid < NTHREADS - 1) ? s_coarse[tid + 1] : 0u;
        if (mine >= TSEL && nxt < TSEL) s_g = tid;
    }
    __syncthreads();
    if (tid == 0) {
        int g = s_g;
        unsigned int cum = (g < NTHREADS - 1) ? s_coarse[g + 1] : 0u;
        int b = g * 8;
        for (int bin = g * 8 + 7; bin >= g * 8; --bin) {
            cum += U.hist[bin];
            if (cum >= TSEL) { b = bin; break; }
        }
        s_bin = b;
    }
    __syncthreads();
    const float thr_float = __uint_as_float(inv_ordered((unsigned int)s_bin << 19));
    __syncthreads();   // all hist reads done before keys alias

    // ---- Pass B: gate via 5 conflict-free LDS.128; guard-free refetch ----
    if (tid < SORT_N) U.s.keys[tid] = 0ull;
    if (tid < 32) s_wc[tid] = 0;
    __syncthreads();
    #pragma unroll 1
    for (int it = 0; it < 5; ++it) {
        float4 bm = s_bmax4[it * NTHREADS + tid];
        const float bms[4] = {bm.x, bm.y, bm.z, bm.w};
        #pragma unroll
        for (int u = 0; u < 4; ++u) {
            if (bms[u] >= thr_float) {     // gate pass implies load in-bounds
                int i = it * (4 * NTHREADS) + u * NTHREADS + tid;
                float4 v = lg4[i];         // L2 hit
                const float vv[4] = {v.x, v.y, v.z, v.w};
                #pragma unroll
                for (int c = 0; c < 4; ++c) {
                    if (vv[c] >= thr_float) {
                        float p = xla_logistic(vv[c]);
                        int pos = atomicAdd(&s_wc[wid], 1);   // 32 banks
                        if (pos < WBUF) {
                            s_wbuf[wid][pos] =
                                ((unsigned long long)__float_as_uint(p) << 32)
                              | (unsigned int)(~(i * 4 + c));
                        }
                    }
                }
            }
        }
    }
    __syncthreads();

    // ---- warp bases via 32-wide scan; copy warp buffers to contiguous keys ----
    if (tid < 32) {
        int c = s_wc[tid]; if (c > WBUF) c = WBUF;
        int v = c;
        #pragma unroll
        for (int off = 1; off < 32; off <<= 1) {
            int u = __shfl_up_sync(0xffffffffu, v, off);
            if (lane >= off) v += u;
        }
        s_wbase[tid] = v - c;
        if (tid == 31) s_cnt = v;
    }
    __syncthreads();
    {
        int myc = s_wc[wid]; if (myc > WBUF) myc = WBUF;
        int base = s_wbase[wid];
        for (int p = lane; p < myc; p += 32) {
            int pos = base + p;
            if (pos < SORT_N) U.s.keys[pos] = s_wbuf[wid][p];
        }
    }
    __syncthreads();
    const int cnt = (s_cnt < SORT_N) ? s_cnt : SORT_N;

    // ---- Sort 256 keys (warps 0-7) || matrix zero + 900-box table (>=256) ----
    if (tid < SORT_N) {
        unsigned long long key = U.s.keys[tid];
        #pragma unroll
        for (int k = 2; k <= 32; k <<= 1)
            key = bitonic_inwarp(key, tid, k, k >> 1);
        U.s.keys[tid] = key;
        BAR256();
        #pragma unroll
        for (int k = 64; k <= SORT_N; k <<= 1) {
            for (int j = k >> 1; j >= 32; j >>= 1) {
                int l = tid ^ j;
                if (l > tid) {
                    unsigned long long a = U.s.keys[tid];
                    unsigned long long b = U.s.keys[l];
                    bool desc = ((tid & k) == 0);
                    if (desc ? (a < b) : (a > b)) {
                        U.s.keys[tid] = b;
                        U.s.keys[l] = a;
                    }
                }
                BAR256();
            }
            key = U.s.keys[tid];
            key = bitonic_inwarp(key, tid, k, 16);
            U.s.keys[tid] = key;
            BAR256();
        }
    } else {
        const int z = tid - SORT_N;            // 0..767
        if (z < MROW * 2) {                    // zero 1024 u64, 2 words each
            s_mat64[z] = 0ull;
            s_mat64[z + MROW * 2] = 0ull;
        }
        if (z < NQ) {
            float4 b = bx4[z];
            s_qbox[z] = make_float4((b.x - 0.5f * b.z) * img_w,
                                    (b.y - 0.5f * b.w) * img_h,
                                    (b.x + 0.5f * b.z) * img_w,
                                    (b.y + 0.5f * b.w) * img_h);
        }
        int q2 = z + 768;
        if (q2 < NQ) {
            float4 b2 = bx4[q2];
            s_qbox[q2] = make_float4((b2.x - 0.5f * b2.z) * img_w,
                                     (b2.y - 0.5f * b2.w) * img_h,
                                     (b2.x + 0.5f * b2.z) * img_w,
                                     (b2.y + 0.5f * b2.w) * img_h);
        }
    }
    __syncthreads();

    // ---- Candidate boxes: gather from SMEM table (no LDG) ----
    if (tid < SORT_N) {
        const int j = tid;
        if (j < cnt) {
            unsigned long long key = U.s.keys[j];
            int idx = (int)(~(unsigned int)key);
            int q = idx / NC, lbl = idx - q * NC;
            float4 bb = s_qbox[q];
            U.s.cbox[j] = bb;
            U.s.area[j] = (bb.z - bb.x) * (bb.w - bb.y);
            U.s.clab[j] = lbl;
        } else {
            U.s.cbox[j] = make_float4(0.f, 0.f, 0.f, 0.f);
            U.s.area[j] = 0.f;
            U.s.clab[j] = -1;
        }
    }
    __syncthreads();

    // ---- Matrix build: sup bits for i,j < 256 (label-gated, div-free) ----
    {
        const int i = tid >> 2;          // 0..255 row owner
        const int seg = tid & 3;         // 0..3 -> j in [seg*64, seg*64+64)
        float4 bi = U.s.cbox[i];
        float  ai = U.s.area[i];
        int    li = U.s.clab[i];
        const int4* clab4 = reinterpret_cast<const int4*>(U.s.clab);
        unsigned int* matw = reinterpret_cast<unsigned int*>(s_mat64);
        #pragma unroll 1
        for (int t = 0; t < 16; ++t) {
            int jb = seg * 64 + t * 4;
            int4 l4 = clab4[jb >> 2];    // LDS.128, 4 labels
            #define CHK(COMP, J)                                                 \
            if ((COMP) == li && li >= 0 && (J) != i) {                           \
                float4 bj = U.s.cbox[J];                                         \
                float xx1 = fmaxf(bi.x, bj.x);                                   \
                float yy1 = fmaxf(bi.y, bj.y);                                   \
                float xx2 = fminf(bi.z, bj.z);                                   \
                float yy2 = fminf(bi.w, bj.w);                                   \
                float inter = fmaxf(xx2 - xx1, 0.f) * fmaxf(yy2 - yy1, 0.f);     \
                float uni = fmaxf(ai + U.s.area[J] - inter, 1e-9f);              \
                if (inter > IOU_THR * uni)                                       \
                    atomicOr(&matw[i * 8 + ((J) >> 5)], 1u << ((J) & 31));       \
            }
            CHK(l4.x, jb + 0)
            CHK(l4.y, jb + 1)
            CHK(l4.z, jb + 2)
            CHK(l4.w, jb + 3)
            #undef CHK
        }
    }
    __syncthreads();

    // ---- Serial walk: ffs over 256-bit not-suppressed mask (1 thread) ----
    if (tid == 0) {
        unsigned long long mk[4] = {0ull, 0ull, 0ull, 0ull};
        int npick = 0;
        const int jmax = cnt;   // cnt <= SORT_N == MROW
        const ulonglong2* mat2 = reinterpret_cast<const ulonglong2*>(s_mat64);
        for (int b = 0; b < 4 && npick < NPOST; ++b) {
            int lim = jmax - b * 64;
            if (lim <= 0) break;
            unsigned long long validm =
                (lim >= 64) ? ~0ull : ((1ull << lim) - 1ull);
            unsigned long long rem = ~mk[b] & validm;
            while (rem && npick < NPOST) {
                int jo = __ffsll((long long)rem) - 1;
                int j = b * 64 + jo;
                s_pkj[npick++] = j;
                ulonglong2 r0 = mat2[j * 2 + 0];
                ulonglong2 r1 = mat2[j * 2 + 1];
                mk[0] |= r0.x;
                mk[1] |= r0.y;
                mk[2] |= r1.x;
                mk[3] |= r1.y;
                unsigned long long above =
                    (jo == 63) ? 0ull : (~0ull << (jo + 1));
                rem = ~mk[b] & validm & above;
            }
        }
        // exhaustion padding (reference: argmax over all -inf = index 0)
        for (; npick < NPOST; ++npick) s_pkj[npick] = 0;
    }
    __syncthreads();

    // ---- Outputs [scores | labels | boxes] f32 (boxes from SMEM table) ----
    if (tid < NPOST) {
        const int k = tid;
        int j = s_pkj[k];
        unsigned long long key = U.s.keys[j];
        float score = __uint_as_float((unsigned int)(key >> 32));
        int idx = (int)(~(unsigned int)key);
        int q = idx / NC, lbl = idx - q * NC;
        float4 bb = s_qbox[q];

        out[(size_t)img * NPOST + k] = score;
        out[(size_t)BS * NPOST + (size_t)img * NPOST + k] = (float)lbl;
        float* ob = out + (size_t)2 * BS * NPOST + ((size_t)img * NPOST + k) * 4;
        ob[0] = bb.x; ob[1] = bb.y; ob[2] = bb.z; ob[3] = bb.w;
    }
}

extern "C" void kernel_launch(void* const* d_in, const int* in_sizes, int n_in,
                              void* d_out, int out_size) {
    const float* pred_logits  = (const float*)d_in[0];
    const float* pred_boxes   = (const float*)d_in[1];
    const float* target_sizes = (const float*)d_in[2];
    float* out = (float*)d_out;
    (void)in_sizes; (void)n_in; (void)out_size;
    const int dyn = 5 * NTHREADS * (int)sizeof(float4);   // 80 KB
    cudaFuncSetAttribute((const void*)nms_post_kernel,
                         cudaFuncAttributeMaxDynamicSharedMemorySize, dyn);
    nms_post_kernel<<<BS, NTHREADS, dyn>>>(pred_logits, pred_boxes, target_sizes, out);
}